// round 16
// baseline (speedup 1.0000x reference)
#include <cuda_runtime.h>
#include <cuda_fp16.h>
#include <math.h>
#include <stdint.h>

// NoisyTopKRouter: B=4, S=4096, D=2048, E=64, K=8
// fp16 2-split (h+l, W pre-scaled 2^10), 3-term mma.sync m16n8k16 f16, Kahan.
// KC=64: half the barriers, double-length MMA bursts.
// out: probs [T*E] f32, topk_idx [T*K] f32, new_bias [E] f32

namespace {

constexpr int T_TOK  = 16384;
constexpr int DDIM   = 2048;
constexpr int E      = 64;
constexpr int KSEL   = 8;
constexpr int TILE_T = 128;
constexpr int KC     = 64;               // fp32 k per chunk
constexpr int NCHUNK = DDIM / KC;        // 32
constexpr int NTHR   = 512;
constexpr int ROWB   = 144;              // 128B data + 16B pad (conflict-free ldsm)
constexpr int A_H = 0;
constexpr int A_L = A_H + TILE_T * ROWB;      // 18432
constexpr int B_H = A_L + TILE_T * ROWB;      // 36864
constexpr int B_L = B_H + 128 * ROWB;         // 55296
constexpr int STAGE_B = B_L + 128 * ROWB;     // 73728
constexpr int CMP_OFF = 2 * STAGE_B;          // 147456
constexpr int SMEM_BYTES = CMP_OFF + 32 * NTHR * 4;   // 212992

constexpr float WSCALE   = 1024.f;            // 2^10 (keeps w_l out of subnormals)
constexpr float WSCALE_I = 1.f / 1024.f;

// Pre-split scaled-W planes: [plane h/l][row 0..127][j 0..511] of uint2 (4 fp16)
__device__ uint2 gW[2][128][512];

__device__ __forceinline__ unsigned h2pack(float hi, float lo) {
    unsigned r; asm("cvt.rn.f16x2.f32 %0, %1, %2;" : "=r"(r) : "f"(hi), "f"(lo)); return r;
}
__device__ __forceinline__ float h2lo(unsigned p) {
    float f; asm("cvt.f32.f16 %0, %1;" : "=f"(f) : "h"((unsigned short)(p & 0xffff)));
    return f;
}
__device__ __forceinline__ float h2hi(unsigned p) {
    float f; asm("cvt.f32.f16 %0, %1;" : "=f"(f) : "h"((unsigned short)(p >> 16)));
    return f;
}

__device__ __forceinline__ void ldsm4(unsigned* r, uint32_t a) {
    asm volatile("ldmatrix.sync.aligned.m8n8.x4.shared.b16 {%0,%1,%2,%3}, [%4];"
                 : "=r"(r[0]), "=r"(r[1]), "=r"(r[2]), "=r"(r[3]) : "r"(a));
}
__device__ __forceinline__ void mma16816(float* d, const unsigned* a, const unsigned* b) {
    asm volatile("mma.sync.aligned.m16n8k16.row.col.f32.f16.f16.f32 "
                 "{%0,%1,%2,%3}, {%4,%5,%6,%7}, {%8,%9}, {%0,%1,%2,%3};"
                 : "+f"(d[0]), "+f"(d[1]), "+f"(d[2]), "+f"(d[3])
                 : "r"(a[0]), "r"(a[1]), "r"(a[2]), "r"(a[3]), "r"(b[0]), "r"(b[1]));
}
__device__ __forceinline__ void cp16(uint32_t dst, const void* src) {
    asm volatile("cp.async.cg.shared.global [%0], [%1], 16;" :: "r"(dst), "l"(src));
}
__device__ __forceinline__ void cp_commit() { asm volatile("cp.async.commit_group;"); }
template <int N>
__device__ __forceinline__ void cp_wait() {
    asm volatile("cp.async.wait_group %0;" :: "n"(N));
}

// 2-way fp16 split of 4 consecutive fp32 (h + l ~= x, residual ~2^-22)
__device__ __forceinline__ void split4h(float4 v, uint2& h, uint2& l) {
    unsigned h0 = h2pack(v.y, v.x), h1 = h2pack(v.w, v.z);
    float r0 = v.x - h2lo(h0), r1 = v.y - h2hi(h0);
    float r2 = v.z - h2lo(h1), r3 = v.w - h2hi(h1);
    h = make_uint2(h0, h1);
    l = make_uint2(h2pack(r1, r0), h2pack(r3, r2));
}

// ---- pre-pass: scale W by 2^10 and split (Wr rows 0-63, Wn rows 64-127) ----
__global__ __launch_bounds__(512)
void wconv_kernel(const float* __restrict__ Wr, const float* __restrict__ Wn)
{
    int f = blockIdx.x * 512 + threadIdx.x;
    if (f >= 128 * 512) return;
    int row = f >> 9, j = f & 511;
    const float* src = (row < 64) ? (Wr + (size_t)row * DDIM)
                                  : (Wn + (size_t)(row - 64) * DDIM);
    float4 v = *reinterpret_cast<const float4*>(src + j * 4);
    v.x *= WSCALE; v.y *= WSCALE; v.z *= WSCALE; v.w *= WSCALE;
    uint2 h, l; split4h(v, h, l);
    gW[0][row][j] = h;
    gW[1][row][j] = l;
}

__global__ __launch_bounds__(NTHR, 1)
void router_kernel(const float* __restrict__ x,
                   const float* __restrict__ bias,
                   const float* __restrict__ nu,
                   float* __restrict__ out_probs,
                   float* __restrict__ out_idx,
                   float* __restrict__ out_bias)
{
    extern __shared__ char sm[];
    const uint32_t smb = (uint32_t)__cvta_generic_to_shared(sm);
    float* cmpS = reinterpret_cast<float*>(sm + CMP_OFF);   // [32][NTHR]

    const int tid  = threadIdx.x;
    const int lane = tid & 31;
    const int wid  = tid >> 5;
    const int token0 = blockIdx.x * TILE_T;

    float acc[2][4][4], mst[2][4][4];
#pragma unroll
    for (int mi = 0; mi < 2; mi++)
#pragma unroll
        for (int ni = 0; ni < 4; ni++)
#pragma unroll
            for (int r = 0; r < 4; r++) { acc[mi][ni][r] = 0.f; mst[mi][ni][r] = 0.f; }
#pragma unroll
    for (int j = 0; j < 32; j++) cmpS[j * NTHR + tid] = 0.f;

    float4 xv[4];
    auto ldg = [&](int c) {
        const int k0 = c * KC;
#pragma unroll
        for (int r = 0; r < 4; r++) {
            int idx = tid + r * NTHR;          // 0..2047
            int row = idx >> 4, kq = idx & 15;
            xv[r] = *reinterpret_cast<const float4*>(
                &x[(size_t)(token0 + row) * DDIM + k0 + kq * 4]);
        }
    };

    auto stsx = [&](int s) {
        char* stage = sm + s * STAGE_B;
#pragma unroll
        for (int r = 0; r < 4; r++) {
            int idx = tid + r * NTHR;
            int row = idx >> 4, kq = idx & 15;
            int off = row * ROWB + kq * 8;
            uint2 h, l; split4h(xv[r], h, l);
            *reinterpret_cast<uint2*>(stage + A_H + off) = h;
            *reinterpret_cast<uint2*>(stage + A_L + off) = l;
        }
    };

    // W tile: 2 planes x 128 rows x 8 x16B = 2048 cp.async -> 4/thread
    auto cpW = [&](int c, int s) {
        const int j0 = c * 16;                 // uint2 column base within a row
        uint32_t base = smb + (uint32_t)(s * STAGE_B + B_H);
#pragma unroll
        for (int r = 0; r < 4; r++) {
            int idx = tid + r * NTHR;          // 0..2047
            int sp = idx >> 10, rem = idx & 1023;
            int row = rem >> 3, q = rem & 7;
            cp16(base + (uint32_t)(sp * (128 * ROWB) + row * ROWB + q * 16),
                 &gW[sp][row][j0 + q * 2]);
        }
        cp_commit();
    };

    const int m0 = (wid & 3) * 32;
    const int n0 = (wid >> 2) * 32;
    const int arow = lane & 15, aoff = (lane >> 4) * 16;
    const int q = lane >> 3;
    const int brow = ((q >> 1) * 8) + (lane & 7), boff = (q & 1) * 16;

    auto compute = [&](int st) {
        const uint32_t sb = smb + (uint32_t)(st * STAGE_B);
#pragma unroll
        for (int s = 0; s < 4; s++) {          // four k16 sub-steps
            unsigned bh[2][4], bl[2][4];
#pragma unroll
            for (int nb = 0; nb < 2; nb++) {
                uint32_t b = sb + B_H + (n0 + 16 * nb + brow) * ROWB + boff + s * 32;
                ldsm4(bh[nb], b);
                ldsm4(bl[nb], b + (B_L - B_H));
            }
#pragma unroll
            for (int mi = 0; mi < 2; mi++) {
                unsigned ah[4], al[4];
                uint32_t a = sb + A_H + (m0 + 16 * mi + arow) * ROWB + aoff + s * 32;
                ldsm4(ah, a);
                ldsm4(al, a + (A_L - A_H));
                // per-accumulator term order: hh, hl, lh
#pragma unroll
                for (int ni = 0; ni < 4; ni++)
                    mma16816(acc[mi][ni], ah, &bh[ni >> 1][(ni & 1) * 2]);  // hh
#pragma unroll
                for (int ni = 0; ni < 4; ni++)
                    mma16816(acc[mi][ni], ah, &bl[ni >> 1][(ni & 1) * 2]);  // hl
#pragma unroll
                for (int ni = 0; ni < 4; ni++)
                    mma16816(acc[mi][ni], al, &bh[ni >> 1][(ni & 1) * 2]);  // lh
            }
        }
    };

    auto drain = [&]() {
#pragma unroll
        for (int mi = 0; mi < 2; mi++)
#pragma unroll
            for (int ni = 0; ni < 4; ni++)
#pragma unroll
                for (int r = 0; r < 4; r++) {
                    int j = ((mi * 4 + ni) * 4 + r);
                    float c0 = cmpS[j * NTHR + tid];
                    float y = acc[mi][ni][r] - c0;
                    float t = mst[mi][ni][r] + y;
                    cmpS[j * NTHR + tid] = (t - mst[mi][ni][r]) - y;
                    mst[mi][ni][r] = t;
                    acc[mi][ni][r] = 0.f;
                }
    };

    // ---- prologue ----
    ldg(0);
    cpW(0, 0);
    stsx(0);
    ldg(1);
    cp_wait<0>();
    __syncthreads();

    // ---- main loop ----
    for (int c = 0; c < NCHUNK; c++) {
        if (c + 1 < NCHUNK) { stsx((c + 1) & 1); cpW(c + 1, (c + 1) & 1); }
        if (c + 2 < NCHUNK) ldg(c + 2);
        compute(c & 1);
        if ((c & 1) == 1) drain();             // every 128 k, same as validated
        cp_wait<0>();
        __syncthreads();
    }

    // ---- store masters to zs [128][130], unscaling by 2^-10 ----
    constexpr int DSTR = 130;
    float* zs = reinterpret_cast<float*>(sm);
    const int dr = lane >> 2, dc = (lane & 3) * 2;
#pragma unroll
    for (int mi = 0; mi < 2; mi++)
#pragma unroll
        for (int ni = 0; ni < 4; ni++) {
            int row = m0 + 16 * mi + dr, col = n0 + 8 * ni + dc;
            *reinterpret_cast<float2*>(&zs[row * DSTR + col]) =
                make_float2(mst[mi][ni][0] * WSCALE_I, mst[mi][ni][1] * WSCALE_I);
            *reinterpret_cast<float2*>(&zs[(row + 8) * DSTR + col]) =
                make_float2(mst[mi][ni][2] * WSCALE_I, mst[mi][ni][3] * WSCALE_I);
        }
    __syncthreads();

    // ---- epilogue: z = u*softplus(noisy) + logit + bias; top-8 + softmax ----
    for (int r = 0; r < 8; r++) {
        int tl = wid * 8 + r;
        size_t t = (size_t)token0 + tl;
        float logit0 = zs[tl * DSTR + lane];
        float logit1 = zs[tl * DSTR + lane + 32];
        float noisy0 = zs[tl * DSTR + 64 + lane];
        float noisy1 = zs[tl * DSTR + 96 + lane];
        float u0 = nu[t * E + lane];
        float u1 = nu[t * E + lane + 32];
        float sp0 = fmaxf(noisy0, 0.f) + log1pf(expf(-fabsf(noisy0)));
        float sp1 = fmaxf(noisy1, 0.f) + log1pf(expf(-fabsf(noisy1)));
        float z0 = fmaf(u0, sp0, logit0 + bias[lane]);
        float z1 = fmaf(u1, sp1, logit1 + bias[lane + 32]);

        float v0 = z0, v1 = z1;
        int sel0 = 0, sel1 = 0;
        float m0s = 0.f, denom = 0.f;
        int myidx = 0;
#pragma unroll
        for (int k = 0; k < KSEL; k++) {
            float bv; int bi;
            if (v0 >= v1) { bv = v0; bi = lane; }
            else          { bv = v1; bi = lane + 32; }
#pragma unroll
            for (int off = 16; off > 0; off >>= 1) {
                float ov = __shfl_xor_sync(0xffffffffu, bv, off);
                int   oi = __shfl_xor_sync(0xffffffffu, bi, off);
                if (ov > bv || (ov == bv && oi < bi)) { bv = ov; bi = oi; }
            }
            if (k == 0) m0s = bv;
            denom += expf(bv - m0s);
            if (lane == k) myidx = bi;
            if (bi == lane)           { v0 = -1e30f; sel0 = 1; }
            else if (bi == lane + 32) { v1 = -1e30f; sel1 = 1; }
        }
        float inv = 1.f / denom;
        out_probs[t * E + lane]      = sel0 ? expf(z0 - m0s) * inv : 0.f;
        out_probs[t * E + lane + 32] = sel1 ? expf(z1 - m0s) * inv : 0.f;
        if (lane < KSEL) out_idx[t * KSEL + lane] = (float)myidx;
    }

    // ---- bias update: sign(avg_load - total_selected) == -1 always ----
    if (blockIdx.x == 0 && tid < E) out_bias[tid] = bias[tid] - 0.001f;
}

} // namespace

extern "C" void kernel_launch(void* const* d_in, const int* in_sizes, int n_in,
                              void* d_out, int out_size)
{
    (void)in_sizes; (void)n_in; (void)out_size;
    const float* x    = (const float*)d_in[0];
    const float* Wr   = (const float*)d_in[1];
    const float* Wn   = (const float*)d_in[2];
    const float* bias = (const float*)d_in[3];
    const float* nu   = (const float*)d_in[4];

    float* out   = (float*)d_out;
    float* probs = out;
    float* idx   = out + (size_t)T_TOK * E;
    float* nb    = idx + (size_t)T_TOK * KSEL;

    wconv_kernel<<<128, 512>>>(Wr, Wn);

    cudaFuncSetAttribute(router_kernel, cudaFuncAttributeMaxDynamicSharedMemorySize,
                         SMEM_BYTES);
    router_kernel<<<T_TOK / TILE_T, NTHR, SMEM_BYTES>>>(x, bias, nu,
                                                        probs, idx, nb);
}